// round 10
// baseline (speedup 1.0000x reference)
#include <cuda_runtime.h>
#include <cuda_bf16.h>
#include <math.h>
#include <stdint.h>

#define DIMS 1024
#define HEAD 16
#define HD   64
#define CTX  2048
#define BATCH 2
#define MROWS (BATCH*CTX)
#define OUT_ELEMS (MROWS*DIMS)
#define QK_ELEMS  ((size_t)BATCH*HEAD*CTX*CTX)

typedef unsigned short u16;
typedef unsigned int   u32;

// ---- scratch ----
__device__ u16 g_xh [MROWS*DIMS], g_xl [MROWS*DIMS];
__device__ u16 g_Wqh[DIMS*DIMS],  g_Wql[DIMS*DIMS];
__device__ u16 g_Wkh[DIMS*DIMS],  g_Wkl[DIMS*DIMS];
__device__ u16 g_Wvh[DIMS*DIMS],  g_Wvl[DIMS*DIMS];
__device__ u16 g_Woh[DIMS*DIMS],  g_Wol[DIMS*DIMS];
__device__ u16 g_Wth[DIMS*DIMS],  g_Wtl[DIMS*DIMS];
__device__ u16 g_W2h[DIMS*DIMS],  g_W2l[DIMS*DIMS];
__device__ float g_b2[DIMS];
__device__ u16 g_qh [MROWS*DIMS], g_ql [MROWS*DIMS];
__device__ u16 g_kh [MROWS*DIMS], g_kl [MROWS*DIMS];
__device__ u16 g_vh [MROWS*DIMS], g_vl [MROWS*DIMS];
__device__ u16 g_avh[MROWS*DIMS], g_avl[MROWS*DIMS];
__device__ float g_kc0[HEAD*MROWS];
__device__ float g_qk_fallback[QK_ELEMS];

// ---- helpers ----
__device__ __forceinline__ u32 smaddr(const void* p){ return (u32)__cvta_generic_to_shared(p); }
__device__ __forceinline__ void ldsm4(u32&r0,u32&r1,u32&r2,u32&r3,u32 a){
    asm volatile("ldmatrix.sync.aligned.m8n8.x4.shared.b16 {%0,%1,%2,%3},[%4];"
        :"=r"(r0),"=r"(r1),"=r"(r2),"=r"(r3):"r"(a));
}
__device__ __forceinline__ void ldsm4t(u32&r0,u32&r1,u32&r2,u32&r3,u32 a){
    asm volatile("ldmatrix.sync.aligned.m8n8.x4.trans.shared.b16 {%0,%1,%2,%3},[%4];"
        :"=r"(r0),"=r"(r1),"=r"(r2),"=r"(r3):"r"(a));
}
__device__ __forceinline__ void mmabf(float c[4],
    u32 a0,u32 a1,u32 a2,u32 a3,u32 b0,u32 b1){
    asm volatile("mma.sync.aligned.m16n8k16.row.col.f32.bf16.bf16.f32 "
        "{%0,%1,%2,%3},{%4,%5,%6,%7},{%8,%9},{%0,%1,%2,%3};"
        :"+f"(c[0]),"+f"(c[1]),"+f"(c[2]),"+f"(c[3])
        :"r"(a0),"r"(a1),"r"(a2),"r"(a3),"r"(b0),"r"(b1));
}
__device__ __forceinline__ u32 packbf(float x, float y){
    __nv_bfloat162 t = __floats2bfloat162_rn(x,y);
    return *reinterpret_cast<u32*>(&t);
}
__device__ __forceinline__ u32 split_pair(float v0, float v1, u32& lo){
    __nv_bfloat16 h0=__float2bfloat16(v0), h1=__float2bfloat16(v1);
    float l0 = v0-__bfloat162float(h0), l1 = v1-__bfloat162float(h1);
    lo = packbf(l0,l1);
    __nv_bfloat162 hh; hh.x=h0; hh.y=h1;
    return *reinterpret_cast<u32*>(&hh);
}
__device__ __forceinline__ void cpa16(u32 dst, const void* src){
    asm volatile("cp.async.cg.shared.global [%0],[%1],16;"::"r"(dst),"l"(src));
}
#define CPA_COMMIT() asm volatile("cp.async.commit_group;"::)
#define CPA_WAIT0()  asm volatile("cp.async.wait_group 0;"::)
#define CPA_WAIT1()  asm volatile("cp.async.wait_group 1;"::)

template<int S>
__device__ __forceinline__ u32 a_addr(u32 base, int r0, int k0, int lane){
    int r = r0 + (lane&7) + ((lane>>3)&1)*8;
    int k = k0 + ((lane>>4)&1)*8;
    return base + (u32)(r*S + k)*2;
}
template<int S>
__device__ __forceinline__ u32 b_addr(u32 base, int n0, int k0, int lane){
    int n = n0 + (lane&7) + ((lane>>4)&1)*8;
    int k = k0 + ((lane>>3)&1)*8;
    return base + (u32)(n*S + k)*2;
}
template<int S>
__device__ __forceinline__ u32 bt_addr(u32 base, int n0, int k0, int lane){
    int k = k0 + (lane&7) + ((lane>>3)&1)*8;
    int n = n0 + ((lane>>4)&1)*8;
    return base + (u32)(k*S + n)*2;
}
__device__ __forceinline__ u32 a_sw(u32 base, int r0, int k0, int lane){
    int r = r0 + (lane&7) + ((lane>>3)&1)*8;
    int c = (k0>>3) + ((lane>>4)&1);
    int ph = c ^ ((r>>1)&3);
    return base + (u32)(r*32 + ph*8)*2;
}
__device__ __forceinline__ u32 b_sw(u32 base, int n0, int k0, int lane){
    int n = n0 + (lane&7) + ((lane>>4)&1)*8;
    int c = (k0>>3) + ((lane>>3)&1);
    int ph = c ^ ((n>>1)&3);
    return base + (u32)(n*32 + ph*8)*2;
}

// ============================================================
// converts
// ============================================================
__global__ void __launch_bounds__(256) conv_split(
    const float* __restrict__ s, u16* __restrict__ h, u16* __restrict__ l, int n)
{
    int i = (blockIdx.x*256 + threadIdx.x)*8;
    if (i >= n) return;
    float4 x0 = *(const float4*)(s+i), x1 = *(const float4*)(s+i+4);
    float xs[8] = {x0.x,x0.y,x0.z,x0.w,x1.x,x1.y,x1.z,x1.w};
    u32 H[4], L[4];
    #pragma unroll
    for (int j=0;j<4;j++) H[j] = split_pair(xs[2*j], xs[2*j+1], L[j]);
    *(uint4*)(h+i) = make_uint4(H[0],H[1],H[2],H[3]);
    *(uint4*)(l+i) = make_uint4(L[0],L[1],L[2],L[3]);
}

struct WPack { const float* s[4]; u16* h[4]; u16* l[4]; };
__global__ void __launch_bounds__(256) conv_w4(WPack p)
{
    int w = blockIdx.y;
    const float* s = p.s[w];
    u16 *h = p.h[w], *l = p.l[w];
    int i = (blockIdx.x*256 + threadIdx.x)*8;
    float4 x0 = *(const float4*)(s+i), x1 = *(const float4*)(s+i+4);
    float xs[8] = {x0.x,x0.y,x0.z,x0.w,x1.x,x1.y,x1.z,x1.w};
    u32 H[4], L[4];
    #pragma unroll
    for (int j=0;j<4;j++) H[j] = split_pair(xs[2*j], xs[2*j+1], L[j]);
    *(uint4*)(h+i) = make_uint4(H[0],H[1],H[2],H[3]);
    *(uint4*)(l+i) = make_uint4(L[0],L[1],L[2],L[3]);
}

__global__ void __launch_bounds__(256) conv_split_t(
    const float* __restrict__ s, u16* __restrict__ h, u16* __restrict__ l)
{
    __shared__ float tile[32][33];
    int bx = blockIdx.x*32, by = blockIdx.y*32;
    int tx = threadIdx.x&31, ty = threadIdx.x>>5;
    for (int i = ty; i < 32; i += 8)
        tile[i][tx] = s[(size_t)(by+i)*DIMS + bx+tx];
    __syncthreads();
    for (int i = ty; i < 32; i += 8) {
        float v = tile[tx][i];
        __nv_bfloat16 hb = __float2bfloat16(v);
        h[(size_t)(bx+i)*DIMS + by+tx] = *(u16*)&hb;
        float lv = v - __bfloat162float(hb);
        __nv_bfloat16 lb = __float2bfloat16(lv);
        l[(size_t)(bx+i)*DIMS + by+tx] = *(u16*)&lb;
    }
}

__global__ void __launch_bounds__(256) bias2_k(
    const float* __restrict__ W, const float* __restrict__ b, float* __restrict__ out)
{
    int n = blockIdx.x*8 + (threadIdx.x>>5);
    int lane = threadIdx.x & 31;
    float s = 0.f;
    for (int k = lane; k < 1024; k += 32) s += b[k] * W[(size_t)n*1024 + k];
    #pragma unroll
    for (int o = 16; o; o >>= 1) s += __shfl_xor_sync(0xffffffffu, s, o);
    if (lane == 0) out[n] = s + b[n];
}

// ============================================================
// bf16x3 GEMM body (unchanged from R9)
// ============================================================
template<bool F32OUT>
__device__ __forceinline__ void gemm_body(
    const u16* __restrict__ Agh, const u16* __restrict__ Agl,
    const u16* __restrict__ Bgh, const u16* __restrict__ Bgl,
    const float* __restrict__ bias,
    u16* __restrict__ Ch, u16* __restrict__ Cl,
    float* __restrict__ Cf, float* __restrict__ kc0,
    int row0, int col0, u16* smp)
{
    int t=threadIdx.x, warp=t>>5, lane=t&31;
    int wm=(warp>>2)*64, wn=(warp&3)*32;
    int gr=lane>>2, gq=lane&3;
    float acc[4][4][4]={};

    int lrow=t>>1, kc2=(t&1)*2;
    const u16* Ash = Agh + (size_t)(row0+lrow)*DIMS + kc2*8;
    const u16* Asl = Agl + (size_t)(row0+lrow)*DIMS + kc2*8;
    const u16* Bsh = Bgh + (size_t)(col0+lrow)*DIMS + kc2*8;
    const u16* Bsl = Bgl + (size_t)(col0+lrow)*DIMS + kc2*8;
    u32 base = smaddr(smp);
    int sw = (lrow>>1)&3;
    u32 d0 = base + (u32)(lrow*32 + (kc2^sw)*8)*2;
    u32 d1 = base + (u32)(lrow*32 + ((kc2+1)^sw)*8)*2;

    auto issue=[&](int it, int st){
        u32 o = (u32)st*32768;
        cpa16(d0+o,        Ash+it*32);  cpa16(d1+o,        Ash+it*32+8);
        cpa16(d0+o+8192,   Asl+it*32);  cpa16(d1+o+8192,   Asl+it*32+8);
        cpa16(d0+o+16384,  Bsh+it*32);  cpa16(d1+o+16384,  Bsh+it*32+8);
        cpa16(d0+o+24576,  Bsl+it*32);  cpa16(d1+o+24576,  Bsl+it*32+8);
        CPA_COMMIT();
    };
    issue(0,0); issue(1,1);

    for (int it=0; it<32; it++){
        int st = it - (it/3)*3;
        CPA_WAIT1();
        __syncthreads();
        if (it+2<32) issue(it+2, (it+2)-((it+2)/3)*3);
        u32 Ah = base + (u32)st*32768;
        u32 Al = Ah+8192, Bh = Ah+16384, Bl = Ah+24576;
        #pragma unroll
        for (int ksi=0;ksi<2;ksi++){
            int kk=ksi*16;
            u32 ah[4][4], al[4][4], bh2[4][2], bl2[4][2];
            #pragma unroll
            for (int m2=0;m2<4;m2++){
                ldsm4(ah[m2][0],ah[m2][1],ah[m2][2],ah[m2][3], a_sw(Ah, wm+m2*16, kk, lane));
                ldsm4(al[m2][0],al[m2][1],al[m2][2],al[m2][3], a_sw(Al, wm+m2*16, kk, lane));
            }
            #pragma unroll
            for (int pp=0;pp<2;pp++){
                u32 r0,r1,r2,r3;
                ldsm4(r0,r1,r2,r3, b_sw(Bh, wn+pp*16, kk, lane));
                bh2[2*pp][0]=r0; bh2[2*pp][1]=r1; bh2[2*pp+1][0]=r2; bh2[2*pp+1][1]=r3;
                ldsm4(r0,r1,r2,r3, b_sw(Bl, wn+pp*16, kk, lane));
                bl2[2*pp][0]=r0; bl2[2*pp][1]=r1; bl2[2*pp+1][0]=r2; bl2[2*pp+1][1]=r3;
            }
            #pragma unroll
            for (int m2=0;m2<4;m2++)
                #pragma unroll
                for (int na=0;na<4;na++){
                    mmabf(acc[m2][na], ah[m2][0],ah[m2][1],ah[m2][2],ah[m2][3], bh2[na][0],bh2[na][1]);
                    mmabf(acc[m2][na], ah[m2][0],ah[m2][1],ah[m2][2],ah[m2][3], bl2[na][0],bl2[na][1]);
                    mmabf(acc[m2][na], al[m2][0],al[m2][1],al[m2][2],al[m2][3], bh2[na][0],bh2[na][1]);
                }
        }
    }
    #pragma unroll
    for (int m2=0;m2<4;m2++)
        #pragma unroll
        for (int na=0;na<4;na++){
            int r  = row0+wm+m2*16+gr;
            int cn = col0+wn+na*8+2*gq;
            float b0v = bias? bias[cn]:0.f, b1v = bias? bias[cn+1]:0.f;
            float v0=acc[m2][na][0]+b0v, v1=acc[m2][na][1]+b1v;
            float v2=acc[m2][na][2]+b0v, v3=acc[m2][na][3]+b1v;
            if (F32OUT){
                *(float2*)(Cf+(size_t)r*DIMS+cn)     = make_float2(v0,v1);
                *(float2*)(Cf+(size_t)(r+8)*DIMS+cn) = make_float2(v2,v3);
            } else {
                u32 lo,hi;
                hi=split_pair(v0,v1,lo);
                *(u32*)(Ch+(size_t)r*DIMS+cn)=hi;  *(u32*)(Cl+(size_t)r*DIMS+cn)=lo;
                hi=split_pair(v2,v3,lo);
                *(u32*)(Ch+(size_t)(r+8)*DIMS+cn)=hi; *(u32*)(Cl+(size_t)(r+8)*DIMS+cn)=lo;
                if (kc0 && gq==0 && (((wn+na*8)&63)==0)){
                    int hh = cn>>6;
                    kc0[hh*MROWS + r]   = v0;
                    kc0[hh*MROWS + r+8] = v2;
                }
            }
        }
}

template<bool F32OUT>
__global__ void __launch_bounds__(256,2) gemm_one(
    const u16* Agh, const u16* Agl, const u16* Bgh, const u16* Bgl,
    const float* bias, u16* Ch, u16* Cl, float* Cf)
{
    extern __shared__ u16 smp[];
    gemm_body<F32OUT>(Agh,Agl,Bgh,Bgl,bias,Ch,Cl,Cf,nullptr,
                      blockIdx.y*128, blockIdx.x*128, smp);
}

__global__ void __launch_bounds__(256,2) gemm_qkv(
    const u16* xh, const u16* xl,
    const u16* wqh, const u16* wql, const u16* wkh, const u16* wkl,
    const u16* wvh, const u16* wvl,
    const float* bq, const float* bv,
    u16* qh, u16* ql, u16* kh, u16* kl, u16* vh, u16* vl, float* kc0)
{
    extern __shared__ u16 smp[];
    int z = blockIdx.z;
    const u16* Bh = (z==0)? wqh : (z==1)? wkh : wvh;
    const u16* Bl = (z==0)? wql : (z==1)? wkl : wvl;
    const float* bias = (z==0)? bq : (z==1)? nullptr : bv;
    u16* Ch = (z==0)? qh : (z==1)? kh : vh;
    u16* Cl = (z==0)? ql : (z==1)? kl : vl;
    float* kc = (z==1)? kc0 : nullptr;
    gemm_body<false>(xh,xl,Bh,Bl,bias,Ch,Cl,nullptr,kc,
                     blockIdx.y*128, blockIdx.x*128, smp);
}

// ============================================================
// Fused attention v2: 256 q-rows/CTA (8 warps x 32 rows), Q cached in regs,
// 32-key chunks, 3-deep cp.async ring, P in registers.
// smem bytes: Qh 36864 | Ql 36864 | KV 3x18432 | gz 3x128
// ============================================================
#define ATT_Q_BYTES   36864
#define ATT_KV_OFF    73728
#define ATT_KVBUF     18432
#define ATT_GZ_OFF    129024
#define ATT_SMEM      129408

__global__ void __launch_bounds__(256,1) attn_fused(
    const u16* __restrict__ qh_g, const u16* __restrict__ ql_g,
    const u16* __restrict__ kh_g, const u16* __restrict__ kl_g,
    const u16* __restrict__ vh_g, const u16* __restrict__ vl_g,
    const float* __restrict__ kc0, const float* __restrict__ factor,
    float* __restrict__ qk, u16* __restrict__ avh_g, u16* __restrict__ avl_g)
{
    extern __shared__ u16 sma[];
    u16 *Qh_p = sma, *Ql_p = sma + ATT_Q_BYTES/2;
    u16 *KV_p = sma + ATT_KV_OFF/2;
    float* gzb = (float*)((char*)sma + ATT_GZ_OFF);

    int t=threadIdx.x, warp=t>>5, lane=t&31;
    int qb=blockIdx.x, bh=blockIdx.y, b=bh>>4, h=bh&15;
    int row0=qb*256, wm=warp*32;
    int gr=lane>>2, gq=lane&3;

    float zfac; { float f=*factor; zfac=fminf(fmaxf(log1pf(expf(f)),0.f),0.001f); }

    // stage Q: 256 rows x 64 cols, h+l (grouped with KV chunk 0)
    {
        int row=t;
        const u16* sh = qh_g + (size_t)(b*CTX+row0+row)*DIMS + h*HD;
        const u16* sl = ql_g + (size_t)(b*CTX+row0+row)*DIMS + h*HD;
        u32 dh = smaddr(Qh_p) + (u32)(row*72)*2;
        u32 dl = smaddr(Ql_p) + (u32)(row*72)*2;
        #pragma unroll
        for (int c=0;c<64;c+=8){ cpa16(dh+c*2, sh+c); cpa16(dl+c*2, sl+c); }
    }
    int krow=t>>3, kseg=(t&7)*8;
    const float* kc0p = kc0 + h*MROWS + b*CTX;
    auto issue_kv=[&](int it, int buf){
        size_t g = (size_t)(b*CTX + it*32 + krow)*DIMS + h*HD + kseg;
        u32 d = smaddr(KV_p) + (u32)buf*ATT_KVBUF + (u32)(krow*72+kseg)*2;
        cpa16(d,        kh_g+g);
        cpa16(d+4608,   kl_g+g);
        cpa16(d+9216,   vh_g+g);
        cpa16(d+13824,  vl_g+g);
        if (t<8) cpa16(smaddr(gzb) + (u32)buf*128 + t*16, kc0p + it*32 + t*4);
        CPA_COMMIT();
    };
    issue_kv(0,0);
    issue_kv(1,1);

    float mA[2][2], sA[2][2];
    #pragma unroll
    for (int i=0;i<2;i++){ mA[i][0]=mA[i][1]=-3.0e38f; sA[i][0]=sA[i][1]=0.f; }
    float acc_o[2][8][4]={};
    u32 qfh[2][4][4], qfl[2][4][4];
    float* Lb = qk + (size_t)bh*CTX*CTX;

    for (int it=0; it<64; it++){
        int buf = it - (it/3)*3;
        u32 Kh = smaddr(KV_p) + (u32)buf*ATT_KVBUF;
        u32 Kl = Kh+4608, Vh = Kh+9216, Vl = Kh+13824;
        CPA_WAIT1();
        __syncthreads();
        if (it==0){
            #pragma unroll
            for (int ma=0;ma<2;ma++)
                #pragma unroll
                for (int ks=0;ks<4;ks++){
                    ldsm4(qfh[ma][ks][0],qfh[ma][ks][1],qfh[ma][ks][2],qfh[ma][ks][3],
                          a_addr<72>(smaddr(Qh_p), wm+ma*16, ks*16, lane));
                    ldsm4(qfl[ma][ks][0],qfl[ma][ks][1],qfl[ma][ks][2],qfl[ma][ks][3],
                          a_addr<72>(smaddr(Ql_p), wm+ma*16, ks*16, lane));
                }
        }
        if (it+2<64){ int nb=(it+2)-((it+2)/3)*3; issue_kv(it+2, nb); }

        // ---- S = Q @ K^T : 32 rows x 32 keys per warp ----
        float sacc[2][4][4]={};
        #pragma unroll
        for (int ks=0;ks<4;ks++){
            u32 bh2[4][2], bl2[4][2];
            #pragma unroll
            for (int pp=0;pp<2;pp++){
                u32 r0,r1,r2,r3;
                ldsm4(r0,r1,r2,r3, b_addr<72>(Kh, pp*16, ks*16, lane));
                bh2[2*pp][0]=r0; bh2[2*pp][1]=r1; bh2[2*pp+1][0]=r2; bh2[2*pp+1][1]=r3;
                ldsm4(r0,r1,r2,r3, b_addr<72>(Kl, pp*16, ks*16, lane));
                bl2[2*pp][0]=r0; bl2[2*pp][1]=r1; bl2[2*pp+1][0]=r2; bl2[2*pp+1][1]=r3;
            }
            #pragma unroll
            for (int ma=0;ma<2;ma++)
                #pragma unroll
                for (int na=0;na<4;na++){
                    mmabf(sacc[ma][na], qfh[ma][ks][0],qfh[ma][ks][1],qfh[ma][ks][2],qfh[ma][ks][3], bh2[na][0],bh2[na][1]);
                    mmabf(sacc[ma][na], qfh[ma][ks][0],qfh[ma][ks][1],qfh[ma][ks][2],qfh[ma][ks][3], bl2[na][0],bl2[na][1]);
                    mmabf(sacc[ma][na], qfl[ma][ks][0],qfl[ma][ks][1],qfl[ma][ks][2],qfl[ma][ks][3], bh2[na][0],bh2[na][1]);
                }
        }
        // ---- gate + scale + spill qk + online softmax ----
        const float* gz = gzb + buf*32;
        int kb = it*32;
        float rs[2][2];
        #pragma unroll
        for (int ma=0;ma<2;ma++){
            int rg0 = row0 + wm + ma*16 + gr;
            float lm0=-3.0e38f, lm1=-3.0e38f;
            #pragma unroll
            for (int na=0;na<4;na++){
                int col=na*8+2*gq;
                float2 gv = *(const float2*)(gz + col);
                float z0 = ((gv.x==0.f)? zfac:1.f)*0.125f;
                float z1 = ((gv.y==0.f)? zfac:1.f)*0.125f;
                sacc[ma][na][0]*=z0; sacc[ma][na][1]*=z1;
                sacc[ma][na][2]*=z0; sacc[ma][na][3]*=z1;
                *(float2*)(Lb+(size_t)rg0*CTX+kb+col)     = make_float2(sacc[ma][na][0],sacc[ma][na][1]);
                *(float2*)(Lb+(size_t)(rg0+8)*CTX+kb+col) = make_float2(sacc[ma][na][2],sacc[ma][na][3]);
                lm0=fmaxf(lm0,fmaxf(sacc[ma][na][0],sacc[ma][na][1]));
                lm1=fmaxf(lm1,fmaxf(sacc[ma][na][2],sacc[ma][na][3]));
            }
            lm0=fmaxf(lm0,__shfl_xor_sync(0xffffffffu,lm0,1));
            lm0=fmaxf(lm0,__shfl_xor_sync(0xffffffffu,lm0,2));
            lm1=fmaxf(lm1,__shfl_xor_sync(0xffffffffu,lm1,1));
            lm1=fmaxf(lm1,__shfl_xor_sync(0xffffffffu,lm1,2));
            float mn0=fmaxf(mA[ma][0],lm0), mn1=fmaxf(mA[ma][1],lm1);
            float r0s=__expf(mA[ma][0]-mn0), r1s=__expf(mA[ma][1]-mn1);
            mA[ma][0]=mn0; mA[ma][1]=mn1;
            sA[ma][0]*=r0s; sA[ma][1]*=r1s;
            rs[ma][0]=r0s; rs[ma][1]=r1s;
            float ps0=0.f, ps1=0.f;
            #pragma unroll
            for (int na=0;na<4;na++){
                sacc[ma][na][0]=__expf(sacc[ma][na][0]-mn0);
                sacc[ma][na][1]=__expf(sacc[ma][na][1]-mn0);
                sacc[ma][na][2]=__expf(sacc[ma][na][2]-mn1);
                sacc[ma][na][3]=__expf(sacc[ma][na][3]-mn1);
                ps0+=sacc[ma][na][0]+sacc[ma][na][1];
                ps1+=sacc[ma][na][2]+sacc[ma][na][3];
            }
            ps0+=__shfl_xor_sync(0xffffffffu,ps0,1); ps0+=__shfl_xor_sync(0xffffffffu,ps0,2);
            ps1+=__shfl_xor_sync(0xffffffffu,ps1,1); ps1+=__shfl_xor_sync(0xffffffffu,ps1,2);
            sA[ma][0]+=ps0; sA[ma][1]+=ps1;
            #pragma unroll
            for (int na=0;na<8;na++){
                acc_o[ma][na][0]*=rs[ma][0]; acc_o[ma][na][1]*=rs[ma][0];
                acc_o[ma][na][2]*=rs[ma][1]; acc_o[ma][na][3]*=rs[ma][1];
            }
        }
        // ---- PV: P in registers ----
        #pragma unroll
        for (int ks=0;ks<2;ks++){
            u32 bh2[8][2], bl2[8][2];
            #pragma unroll
            for (int pp=0;pp<4;pp++){
                u32 r0,r1,r2,r3;
                ldsm4t(r0,r1,r2,r3, bt_addr<72>(Vh, pp*16, ks*16, lane));
                bh2[2*pp][0]=r0; bh2[2*pp][1]=r1; bh2[2*pp+1][0]=r2; bh2[2*pp+1][1]=r3;
                ldsm4t(r0,r1,r2,r3, bt_addr<72>(Vl, pp*16, ks*16, lane));
                bl2[2*pp][0]=r0; bl2[2*pp][1]=r1; bl2[2*pp+1][0]=r2; bl2[2*pp+1][1]=r3;
            }
            #pragma unroll
            for (int ma=0;ma<2;ma++){
                u32 pa[4], pl2[4];
                pa[0]=split_pair(sacc[ma][2*ks][0],  sacc[ma][2*ks][1],  pl2[0]);
                pa[1]=split_pair(sacc[ma][2*ks][2],  sacc[ma][2*ks][3],  pl2[1]);
                pa[2]=split_pair(sacc[ma][2*ks+1][0],sacc[ma][2*ks+1][1],pl2[2]);
                pa[3]=split_pair(sacc[ma][2*ks+1][2],sacc[ma][2*ks+1][3],pl2[3]);
                #pragma unroll
                for (int na=0;na<8;na++){
                    mmabf(acc_o[ma][na], pa[0],pa[1],pa[2],pa[3], bh2[na][0],bh2[na][1]);
                    mmabf(acc_o[ma][na], pa[0],pa[1],pa[2],pa[3], bl2[na][0],bl2[na][1]);
                    mmabf(acc_o[ma][na], pl2[0],pl2[1],pl2[2],pl2[3], bh2[na][0],bh2[na][1]);
                }
            }
        }
    }
    // epilogue
    #pragma unroll
    for (int ma=0;ma<2;ma++){
        int rg0 = row0 + wm + ma*16 + gr;
        float i0=1.f/sA[ma][0], i1=1.f/sA[ma][1];
        #pragma unroll
        for (int na=0;na<8;na++){
            int col=na*8+2*gq;
            size_t o0=(size_t)(b*CTX+rg0)*DIMS + h*HD + col;
            size_t o1=(size_t)(b*CTX+rg0+8)*DIMS + h*HD + col;
            u32 lo,hi;
            hi=split_pair(acc_o[ma][na][0]*i0, acc_o[ma][na][1]*i0, lo);
            *(u32*)(avh_g+o0)=hi; *(u32*)(avl_g+o0)=lo;
            hi=split_pair(acc_o[ma][na][2]*i1, acc_o[ma][na][3]*i1, lo);
            *(u32*)(avh_g+o1)=hi; *(u32*)(avl_g+o1)=lo;
        }
    }
}

// ============================================================
extern "C" void kernel_launch(void* const* d_in, const int* in_sizes, int n_in,
                              void* d_out, int out_size)
{
    const float* x    = (const float*)d_in[0];
    const float* Wq   = (const float*)d_in[1];
    const float* bq   = (const float*)d_in[2];
    const float* Wk   = (const float*)d_in[3];
    const float* Wv   = (const float*)d_in[4];
    const float* bv   = (const float*)d_in[5];
    const float* Wout = (const float*)d_in[6];
    const float* bout = (const float*)d_in[7];
    const float* factor = (const float*)d_in[8];

    u16 *xh,*xl,*wqh,*wql,*wkh,*wkl,*wvh,*wvl,*woh,*wol,*wth,*wtl,*w2h,*w2l;
    u16 *qh,*ql,*kh,*kl,*vh,*vl,*avh,*avl;
    float *b2,*kc0,*qkfb;
    cudaGetSymbolAddress((void**)&xh,  g_xh);  cudaGetSymbolAddress((void**)&xl,  g_xl);
    cudaGetSymbolAddress((void**)&wqh, g_Wqh); cudaGetSymbolAddress((void**)&wql, g_Wql);
    cudaGetSymbolAddress((void**)&wkh, g_Wkh); cudaGetSymbolAddress((void**)&wkl, g_Wkl);
    cudaGetSymbolAddress((void**)&wvh, g_Wvh); cudaGetSymbolAddress((void**)&wvl, g_Wvl);
    cudaGetSymbolAddress((void**)&woh, g_Woh); cudaGetSymbolAddress((void**)&wol, g_Wol);
    cudaGetSymbolAddress((void**)&wth, g_Wth); cudaGetSymbolAddress((void**)&wtl, g_Wtl);
    cudaGetSymbolAddress((void**)&w2h, g_W2h); cudaGetSymbolAddress((void**)&w2l, g_W2l);
    cudaGetSymbolAddress((void**)&qh,  g_qh);  cudaGetSymbolAddress((void**)&ql,  g_ql);
    cudaGetSymbolAddress((void**)&kh,  g_kh);  cudaGetSymbolAddress((void**)&kl,  g_kl);
    cudaGetSymbolAddress((void**)&vh,  g_vh);  cudaGetSymbolAddress((void**)&vl,  g_vl);
    cudaGetSymbolAddress((void**)&avh, g_avh); cudaGetSymbolAddress((void**)&avl, g_avl);
    cudaGetSymbolAddress((void**)&b2,  g_b2);
    cudaGetSymbolAddress((void**)&kc0, g_kc0);
    cudaGetSymbolAddress((void**)&qkfb, g_qk_fallback);

    float* out = (float*)d_out;
    float* qkdst = ((size_t)out_size >= (size_t)OUT_ELEMS + QK_ELEMS)
                 ? (out + OUT_ELEMS) : qkfb;

    const int GSM = 98304;
    cudaFuncSetAttribute(gemm_qkv,       cudaFuncAttributeMaxDynamicSharedMemorySize, GSM);
    cudaFuncSetAttribute(gemm_one<false>,cudaFuncAttributeMaxDynamicSharedMemorySize, GSM);
    cudaFuncSetAttribute(gemm_one<true>, cudaFuncAttributeMaxDynamicSharedMemorySize, GSM);
    cudaFuncSetAttribute(attn_fused,     cudaFuncAttributeMaxDynamicSharedMemorySize, ATT_SMEM);

    // converts
    conv_split<<<2048,256>>>(x, xh, xl, MROWS*DIMS);
    WPack wp;
    wp.s[0]=Wq;  wp.h[0]=wqh; wp.l[0]=wql;
    wp.s[1]=Wk;  wp.h[1]=wkh; wp.l[1]=wkl;
    wp.s[2]=Wv;  wp.h[2]=wvh; wp.l[2]=wvl;
    wp.s[3]=Wout;wp.h[3]=woh; wp.l[3]=wol;
    conv_w4<<<dim3(512,4),256>>>(wp);
    conv_split_t<<<dim3(32,32),256>>>(Wout, wth, wtl);
    bias2_k<<<128,256>>>(Wout, bout, b2);

    // W2 = Wout @ Wout
    gemm_one<false><<<dim3(8,8), 256, GSM>>>(woh, wol, wth, wtl, nullptr, w2h, w2l, nullptr);

    // fused QKV projections
    gemm_qkv<<<dim3(8,32,3), 256, GSM>>>(xh,xl, wqh,wql,wkh,wkl,wvh,wvl,
                                         bq,bv, qh,ql,kh,kl,vh,vl, kc0);

    // fused attention (spills qk)
    attn_fused<<<dim3(8,32), 256, ATT_SMEM>>>(qh,ql,kh,kl,vh,vl, kc0, factor, qkdst, avh, avl);

    // out = wv @ W2^T + b2
    gemm_one<true><<<dim3(8,32), 256, GSM>>>(avh, avl, w2h, w2l, b2, nullptr, nullptr, out);
}

// round 11
// speedup vs baseline: 1.0170x; 1.0170x over previous
#include <cuda_runtime.h>
#include <cuda_bf16.h>
#include <math.h>
#include <stdint.h>

#define DIMS 1024
#define HEAD 16
#define HD   64
#define CTX  2048
#define BATCH 2
#define MROWS (BATCH*CTX)
#define OUT_ELEMS (MROWS*DIMS)
#define QK_ELEMS  ((size_t)BATCH*HEAD*CTX*CTX)

typedef unsigned short u16;
typedef unsigned int   u32;

// ---- scratch ----
__device__ u16 g_xh [MROWS*DIMS], g_xl [MROWS*DIMS];
__device__ u16 g_Wqh[DIMS*DIMS],  g_Wql[DIMS*DIMS];
__device__ u16 g_Wkh[DIMS*DIMS],  g_Wkl[DIMS*DIMS];
__device__ u16 g_Wvh[DIMS*DIMS],  g_Wvl[DIMS*DIMS];
__device__ u16 g_Woh[DIMS*DIMS],  g_Wol[DIMS*DIMS];
__device__ u16 g_Wth[DIMS*DIMS],  g_Wtl[DIMS*DIMS];
__device__ u16 g_W2h[DIMS*DIMS],  g_W2l[DIMS*DIMS];
__device__ float g_b2[DIMS];
__device__ u16 g_qh [MROWS*DIMS], g_ql [MROWS*DIMS];
__device__ u16 g_kh [MROWS*DIMS], g_kl [MROWS*DIMS];
__device__ u16 g_vh [MROWS*DIMS], g_vl [MROWS*DIMS];
__device__ u16 g_avh[MROWS*DIMS], g_avl[MROWS*DIMS];
__device__ float g_kc0[HEAD*MROWS];
__device__ float g_qk_fallback[QK_ELEMS];

// ---- helpers ----
__device__ __forceinline__ u32 smaddr(const void* p){ return (u32)__cvta_generic_to_shared(p); }
__device__ __forceinline__ void ldsm4(u32&r0,u32&r1,u32&r2,u32&r3,u32 a){
    asm volatile("ldmatrix.sync.aligned.m8n8.x4.shared.b16 {%0,%1,%2,%3},[%4];"
        :"=r"(r0),"=r"(r1),"=r"(r2),"=r"(r3):"r"(a));
}
__device__ __forceinline__ void ldsm4t(u32&r0,u32&r1,u32&r2,u32&r3,u32 a){
    asm volatile("ldmatrix.sync.aligned.m8n8.x4.trans.shared.b16 {%0,%1,%2,%3},[%4];"
        :"=r"(r0),"=r"(r1),"=r"(r2),"=r"(r3):"r"(a));
}
__device__ __forceinline__ void mmabf(float c[4],
    u32 a0,u32 a1,u32 a2,u32 a3,u32 b0,u32 b1){
    asm volatile("mma.sync.aligned.m16n8k16.row.col.f32.bf16.bf16.f32 "
        "{%0,%1,%2,%3},{%4,%5,%6,%7},{%8,%9},{%0,%1,%2,%3};"
        :"+f"(c[0]),"+f"(c[1]),"+f"(c[2]),"+f"(c[3])
        :"r"(a0),"r"(a1),"r"(a2),"r"(a3),"r"(b0),"r"(b1));
}
__device__ __forceinline__ u32 packbf(float x, float y){
    __nv_bfloat162 t = __floats2bfloat162_rn(x,y);
    return *reinterpret_cast<u32*>(&t);
}
__device__ __forceinline__ u32 split_pair(float v0, float v1, u32& lo){
    __nv_bfloat16 h0=__float2bfloat16(v0), h1=__float2bfloat16(v1);
    float l0 = v0-__bfloat162float(h0), l1 = v1-__bfloat162float(h1);
    lo = packbf(l0,l1);
    __nv_bfloat162 hh; hh.x=h0; hh.y=h1;
    return *reinterpret_cast<u32*>(&hh);
}
__device__ __forceinline__ void cpa16(u32 dst, const void* src){
    asm volatile("cp.async.cg.shared.global [%0],[%1],16;"::"r"(dst),"l"(src));
}
#define CPA_COMMIT() asm volatile("cp.async.commit_group;"::)
#define CPA_WAIT0()  asm volatile("cp.async.wait_group 0;"::)
#define CPA_WAIT1()  asm volatile("cp.async.wait_group 1;"::)

template<int S>
__device__ __forceinline__ u32 a_addr(u32 base, int r0, int k0, int lane){
    int r = r0 + (lane&7) + ((lane>>3)&1)*8;
    int k = k0 + ((lane>>4)&1)*8;
    return base + (u32)(r*S + k)*2;
}
template<int S>
__device__ __forceinline__ u32 b_addr(u32 base, int n0, int k0, int lane){
    int n = n0 + (lane&7) + ((lane>>4)&1)*8;
    int k = k0 + ((lane>>3)&1)*8;
    return base + (u32)(n*S + k)*2;
}
template<int S>
__device__ __forceinline__ u32 bt_addr(u32 base, int n0, int k0, int lane){
    int k = k0 + (lane&7) + ((lane>>3)&1)*8;
    int n = n0 + ((lane>>4)&1)*8;
    return base + (u32)(k*S + n)*2;
}
__device__ __forceinline__ u32 a_sw(u32 base, int r0, int k0, int lane){
    int r = r0 + (lane&7) + ((lane>>3)&1)*8;
    int c = (k0>>3) + ((lane>>4)&1);
    int ph = c ^ ((r>>1)&3);
    return base + (u32)(r*32 + ph*8)*2;
}
__device__ __forceinline__ u32 b_sw(u32 base, int n0, int k0, int lane){
    int n = n0 + (lane&7) + ((lane>>4)&1)*8;
    int c = (k0>>3) + ((lane>>3)&1);
    int ph = c ^ ((n>>1)&3);
    return base + (u32)(n*32 + ph*8)*2;
}

// ============================================================
// converts
// ============================================================
__global__ void __launch_bounds__(256) conv_split(
    const float* __restrict__ s, u16* __restrict__ h, u16* __restrict__ l, int n)
{
    int i = (blockIdx.x*256 + threadIdx.x)*8;
    if (i >= n) return;
    float4 x0 = *(const float4*)(s+i), x1 = *(const float4*)(s+i+4);
    float xs[8] = {x0.x,x0.y,x0.z,x0.w,x1.x,x1.y,x1.z,x1.w};
    u32 H[4], L[4];
    #pragma unroll
    for (int j=0;j<4;j++) H[j] = split_pair(xs[2*j], xs[2*j+1], L[j]);
    *(uint4*)(h+i) = make_uint4(H[0],H[1],H[2],H[3]);
    *(uint4*)(l+i) = make_uint4(L[0],L[1],L[2],L[3]);
}

struct WPack { const float* s[4]; u16* h[4]; u16* l[4]; };
__global__ void __launch_bounds__(256) conv_w4(WPack p)
{
    int w = blockIdx.y;
    const float* s = p.s[w];
    u16 *h = p.h[w], *l = p.l[w];
    int i = (blockIdx.x*256 + threadIdx.x)*8;
    float4 x0 = *(const float4*)(s+i), x1 = *(const float4*)(s+i+4);
    float xs[8] = {x0.x,x0.y,x0.z,x0.w,x1.x,x1.y,x1.z,x1.w};
    u32 H[4], L[4];
    #pragma unroll
    for (int j=0;j<4;j++) H[j] = split_pair(xs[2*j], xs[2*j+1], L[j]);
    *(uint4*)(h+i) = make_uint4(H[0],H[1],H[2],H[3]);
    *(uint4*)(l+i) = make_uint4(L[0],L[1],L[2],L[3]);
}

__global__ void __launch_bounds__(256) conv_split_t(
    const float* __restrict__ s, u16* __restrict__ h, u16* __restrict__ l)
{
    __shared__ float tile[32][33];
    int bx = blockIdx.x*32, by = blockIdx.y*32;
    int tx = threadIdx.x&31, ty = threadIdx.x>>5;
    for (int i = ty; i < 32; i += 8)
        tile[i][tx] = s[(size_t)(by+i)*DIMS + bx+tx];
    __syncthreads();
    for (int i = ty; i < 32; i += 8) {
        float v = tile[tx][i];
        __nv_bfloat16 hb = __float2bfloat16(v);
        h[(size_t)(bx+i)*DIMS + by+tx] = *(u16*)&hb;
        float lv = v - __bfloat162float(hb);
        __nv_bfloat16 lb = __float2bfloat16(lv);
        l[(size_t)(bx+i)*DIMS + by+tx] = *(u16*)&lb;
    }
}

__global__ void __launch_bounds__(256) bias2_k(
    const float* __restrict__ W, const float* __restrict__ b, float* __restrict__ out)
{
    int n = blockIdx.x*8 + (threadIdx.x>>5);
    int lane = threadIdx.x & 31;
    float s = 0.f;
    for (int k = lane; k < 1024; k += 32) s += b[k] * W[(size_t)n*1024 + k];
    #pragma unroll
    for (int o = 16; o; o >>= 1) s += __shfl_xor_sync(0xffffffffu, s, o);
    if (lane == 0) out[n] = s + b[n];
}

// ============================================================
// bf16x3 GEMM body (unchanged)
// ============================================================
template<bool F32OUT>
__device__ __forceinline__ void gemm_body(
    const u16* __restrict__ Agh, const u16* __restrict__ Agl,
    const u16* __restrict__ Bgh, const u16* __restrict__ Bgl,
    const float* __restrict__ bias,
    u16* __restrict__ Ch, u16* __restrict__ Cl,
    float* __restrict__ Cf, float* __restrict__ kc0,
    int row0, int col0, u16* smp)
{
    int t=threadIdx.x, warp=t>>5, lane=t&31;
    int wm=(warp>>2)*64, wn=(warp&3)*32;
    int gr=lane>>2, gq=lane&3;
    float acc[4][4][4]={};

    int lrow=t>>1, kc2=(t&1)*2;
    const u16* Ash = Agh + (size_t)(row0+lrow)*DIMS + kc2*8;
    const u16* Asl = Agl + (size_t)(row0+lrow)*DIMS + kc2*8;
    const u16* Bsh = Bgh + (size_t)(col0+lrow)*DIMS + kc2*8;
    const u16* Bsl = Bgl + (size_t)(col0+lrow)*DIMS + kc2*8;
    u32 base = smaddr(smp);
    int sw = (lrow>>1)&3;
    u32 d0 = base + (u32)(lrow*32 + (kc2^sw)*8)*2;
    u32 d1 = base + (u32)(lrow*32 + ((kc2+1)^sw)*8)*2;

    auto issue=[&](int it, int st){
        u32 o = (u32)st*32768;
        cpa16(d0+o,        Ash+it*32);  cpa16(d1+o,        Ash+it*32+8);
        cpa16(d0+o+8192,   Asl+it*32);  cpa16(d1+o+8192,   Asl+it*32+8);
        cpa16(d0+o+16384,  Bsh+it*32);  cpa16(d1+o+16384,  Bsh+it*32+8);
        cpa16(d0+o+24576,  Bsl+it*32);  cpa16(d1+o+24576,  Bsl+it*32+8);
        CPA_COMMIT();
    };
    issue(0,0); issue(1,1);

    for (int it=0; it<32; it++){
        int st = it - (it/3)*3;
        CPA_WAIT1();
        __syncthreads();
        if (it+2<32) issue(it+2, (it+2)-((it+2)/3)*3);
        u32 Ah = base + (u32)st*32768;
        u32 Al = Ah+8192, Bh = Ah+16384, Bl = Ah+24576;
        #pragma unroll
        for (int ksi=0;ksi<2;ksi++){
            int kk=ksi*16;
            u32 ah[4][4], al[4][4], bh2[4][2], bl2[4][2];
            #pragma unroll
            for (int m2=0;m2<4;m2++){
                ldsm4(ah[m2][0],ah[m2][1],ah[m2][2],ah[m2][3], a_sw(Ah, wm+m2*16, kk, lane));
                ldsm4(al[m2][0],al[m2][1],al[m2][2],al[m2][3], a_sw(Al, wm+m2*16, kk, lane));
            }
            #pragma unroll
            for (int pp=0;pp<2;pp++){
                u32 r0,r1,r2,r3;
                ldsm4(r0,r1,r2,r3, b_sw(Bh, wn+pp*16, kk, lane));
                bh2[2*pp][0]=r0; bh2[2*pp][1]=r1; bh2[2*pp+1][0]=r2; bh2[2*pp+1][1]=r3;
                ldsm4(r0,r1,r2,r3, b_sw(Bl, wn+pp*16, kk, lane));
                bl2[2*pp][0]=r0; bl2[2*pp][1]=r1; bl2[2*pp+1][0]=r2; bl2[2*pp+1][1]=r3;
            }
            #pragma unroll
            for (int m2=0;m2<4;m2++)
                #pragma unroll
                for (int na=0;na<4;na++){
                    mmabf(acc[m2][na], ah[m2][0],ah[m2][1],ah[m2][2],ah[m2][3], bh2[na][0],bh2[na][1]);
                    mmabf(acc[m2][na], ah[m2][0],ah[m2][1],ah[m2][2],ah[m2][3], bl2[na][0],bl2[na][1]);
                    mmabf(acc[m2][na], al[m2][0],al[m2][1],al[m2][2],al[m2][3], bh2[na][0],bh2[na][1]);
                }
        }
    }
    #pragma unroll
    for (int m2=0;m2<4;m2++)
        #pragma unroll
        for (int na=0;na<4;na++){
            int r  = row0+wm+m2*16+gr;
            int cn = col0+wn+na*8+2*gq;
            float b0v = bias? bias[cn]:0.f, b1v = bias? bias[cn+1]:0.f;
            float v0=acc[m2][na][0]+b0v, v1=acc[m2][na][1]+b1v;
            float v2=acc[m2][na][2]+b0v, v3=acc[m2][na][3]+b1v;
            if (F32OUT){
                *(float2*)(Cf+(size_t)r*DIMS+cn)     = make_float2(v0,v1);
                *(float2*)(Cf+(size_t)(r+8)*DIMS+cn) = make_float2(v2,v3);
            } else {
                u32 lo,hi;
                hi=split_pair(v0,v1,lo);
                *(u32*)(Ch+(size_t)r*DIMS+cn)=hi;  *(u32*)(Cl+(size_t)r*DIMS+cn)=lo;
                hi=split_pair(v2,v3,lo);
                *(u32*)(Ch+(size_t)(r+8)*DIMS+cn)=hi; *(u32*)(Cl+(size_t)(r+8)*DIMS+cn)=lo;
                if (kc0 && gq==0 && (((wn+na*8)&63)==0)){
                    int hh = cn>>6;
                    kc0[hh*MROWS + r]   = v0;
                    kc0[hh*MROWS + r+8] = v2;
                }
            }
        }
}

template<bool F32OUT>
__global__ void __launch_bounds__(256,2) gemm_one(
    const u16* Agh, const u16* Agl, const u16* Bgh, const u16* Bgl,
    const float* bias, u16* Ch, u16* Cl, float* Cf)
{
    extern __shared__ u16 smp[];
    gemm_body<F32OUT>(Agh,Agl,Bgh,Bgl,bias,Ch,Cl,Cf,nullptr,
                      blockIdx.y*128, blockIdx.x*128, smp);
}

__global__ void __launch_bounds__(256,2) gemm_qkv(
    const u16* xh, const u16* xl,
    const u16* wqh, const u16* wql, const u16* wkh, const u16* wkl,
    const u16* wvh, const u16* wvl,
    const float* bq, const float* bv,
    u16* qh, u16* ql, u16* kh, u16* kl, u16* vh, u16* vl, float* kc0)
{
    extern __shared__ u16 smp[];
    int z = blockIdx.z;
    const u16* Bh = (z==0)? wqh : (z==1)? wkh : wvh;
    const u16* Bl = (z==0)? wql : (z==1)? wkl : wvl;
    const float* bias = (z==0)? bq : (z==1)? nullptr : bv;
    u16* Ch = (z==0)? qh : (z==1)? kh : vh;
    u16* Cl = (z==0)? ql : (z==1)? kl : vl;
    float* kc = (z==1)? kc0 : nullptr;
    gemm_body<false>(xh,xl,Bh,Bl,bias,Ch,Cl,nullptr,kc,
                     blockIdx.y*128, blockIdx.x*128, smp);
}

// ============================================================
// Fused attention (R9 tiling, ring-3): 128 q-rows/CTA, 8 warps x 16 rows,
// 32-key chunks, 3-deep cp.async KV ring (wait_group 1), P in registers.
// smem (u16 idx): Qh 0, Ql 9216, KV 18432 (+9216/buf x3), gz floats @46080
// total bytes = 92160 + 384 = 92544; 2 CTA/SM.
// ============================================================
#define ATT_SMEM 92544

__global__ void __launch_bounds__(256,2) attn_fused(
    const u16* __restrict__ qh_g, const u16* __restrict__ ql_g,
    const u16* __restrict__ kh_g, const u16* __restrict__ kl_g,
    const u16* __restrict__ vh_g, const u16* __restrict__ vl_g,
    const float* __restrict__ kc0, const float* __restrict__ factor,
    float* __restrict__ qk, u16* __restrict__ avh_g, u16* __restrict__ avl_g)
{
    extern __shared__ u16 sma[];
    u16 *Qh_p = sma, *Ql_p = sma+9216, *KV_p = sma+18432;
    float* gzb = (float*)(sma + 46080);

    int t=threadIdx.x, warp=t>>5, lane=t&31;
    int qb=blockIdx.x, bh=blockIdx.y, b=bh>>4, h=bh&15;
    int row0=qb*128, wm=warp*16;
    int gr=lane>>2, gq=lane&3;

    float zfac; { float f=*factor; zfac=fminf(fmaxf(log1pf(expf(f)),0.f),0.001f); }

    // stage Q (grouped with KV chunk 0)
    {
        int row=t>>1, half=(t&1)*32;
        const u16* sh = qh_g + (size_t)(b*CTX+row0+row)*DIMS + h*HD + half;
        const u16* sl = ql_g + (size_t)(b*CTX+row0+row)*DIMS + h*HD + half;
        u32 dh = smaddr(Qh_p) + (u32)(row*72+half)*2;
        u32 dl = smaddr(Ql_p) + (u32)(row*72+half)*2;
        #pragma unroll
        for (int c=0;c<32;c+=8){ cpa16(dh+c*2, sh+c); cpa16(dl+c*2, sl+c); }
    }
    int krow=t>>3, kseg=(t&7)*8;
    const float* kc0p = kc0 + h*MROWS + b*CTX;
    auto issue_kv=[&](int it, int buf){
        size_t g = (size_t)(b*CTX + it*32 + krow)*DIMS + h*HD + kseg;
        u32 d = smaddr(KV_p) + (u32)buf*18432 + (u32)(krow*72+kseg)*2;
        cpa16(d,        kh_g+g);
        cpa16(d+4608,   kl_g+g);
        cpa16(d+9216,   vh_g+g);
        cpa16(d+13824,  vl_g+g);
        if (t<8) cpa16(smaddr(gzb) + (u32)buf*128 + t*16, kc0p + it*32 + t*4);
        CPA_COMMIT();
    };
    issue_kv(0,0);
    issue_kv(1,1);

    float m0=-3.0e38f, m1=-3.0e38f, s0=0.f, s1=0.f;
    float acc_o[8][4]={};
    u32 qfh[4][4], qfl[4][4];
    float* Lb = qk + (size_t)bh*CTX*CTX;
    int rg0 = row0+wm+gr;

    for (int it=0; it<64; it++){
        int buf = it - (it/3)*3;
        u32 Kh = smaddr(KV_p) + (u32)buf*18432;
        u32 Kl = Kh+4608, Vh = Kh+9216, Vl = Kh+13824;
        CPA_WAIT1();
        __syncthreads();
        if (it==0){
            #pragma unroll
            for (int ks=0;ks<4;ks++){
                ldsm4(qfh[ks][0],qfh[ks][1],qfh[ks][2],qfh[ks][3], a_addr<72>(smaddr(Qh_p), wm, ks*16, lane));
                ldsm4(qfl[ks][0],qfl[ks][1],qfl[ks][2],qfl[ks][3], a_addr<72>(smaddr(Ql_p), wm, ks*16, lane));
            }
        }
        if (it+2<64){ int nb=(it+2)-((it+2)/3)*3; issue_kv(it+2, nb); }

        // S = Q @ K^T  (16 rows x 32 keys per warp)
        float sacc[4][4]={};
        #pragma unroll
        for (int ks=0;ks<4;ks++){
            u32 bh2[4][2], bl2[4][2];
            #pragma unroll
            for (int pp=0;pp<2;pp++){
                u32 r0,r1,r2,r3;
                ldsm4(r0,r1,r2,r3, b_addr<72>(Kh, pp*16, ks*16, lane));
                bh2[2*pp][0]=r0; bh2[2*pp][1]=r1; bh2[2*pp+1][0]=r2; bh2[2*pp+1][1]=r3;
                ldsm4(r0,r1,r2,r3, b_addr<72>(Kl, pp*16, ks*16, lane));
                bl2[2*pp][0]=r0; bl2[2*pp][1]=r1; bl2[2*pp+1][0]=r2; bl2[2*pp+1][1]=r3;
            }
            #pragma unroll
            for (int na=0;na<4;na++){
                mmabf(sacc[na], qfh[ks][0],qfh[ks][1],qfh[ks][2],qfh[ks][3], bh2[na][0],bh2[na][1]);
                mmabf(sacc[na], qfh[ks][0],qfh[ks][1],qfh[ks][2],qfh[ks][3], bl2[na][0],bl2[na][1]);
                mmabf(sacc[na], qfl[ks][0],qfl[ks][1],qfl[ks][2],qfl[ks][3], bh2[na][0],bh2[na][1]);
            }
        }
        // gate + scale + spill qk + row max
        const float* gz = gzb + buf*32;
        float lm0=-3.0e38f, lm1=-3.0e38f;
        int kb = it*32;
        #pragma unroll
        for (int na=0;na<4;na++){
            int col=na*8+2*gq;
            float2 gv = *(const float2*)(gz + col);
            float z0 = ((gv.x==0.f)? zfac:1.f)*0.125f;
            float z1 = ((gv.y==0.f)? zfac:1.f)*0.125f;
            sacc[na][0]*=z0; sacc[na][1]*=z1; sacc[na][2]*=z0; sacc[na][3]*=z1;
            *(float2*)(Lb+(size_t)rg0*CTX+kb+col)     = make_float2(sacc[na][0],sacc[na][1]);
            *(float2*)(Lb+(size_t)(rg0+8)*CTX+kb+col) = make_float2(sacc[na][2],sacc[na][3]);
            lm0=fmaxf(lm0,fmaxf(sacc[na][0],sacc[na][1]));
            lm1=fmaxf(lm1,fmaxf(sacc[na][2],sacc[na][3]));
        }
        lm0=fmaxf(lm0,__shfl_xor_sync(0xffffffffu,lm0,1));
        lm0=fmaxf(lm0,__shfl_xor_sync(0xffffffffu,lm0,2));
        lm1=fmaxf(lm1,__shfl_xor_sync(0xffffffffu,lm1,1));
        lm1=fmaxf(lm1,__shfl_xor_sync(0xffffffffu,lm1,2));
        float mn0=fmaxf(m0,lm0), mn1=fmaxf(m1,lm1);
        float r0s=__expf(m0-mn0), r1s=__expf(m1-mn1);
        m0=mn0; m1=mn1; s0*=r0s; s1*=r1s;
        float ps0=0.f, ps1=0.f;
        #pragma unroll
        for (int na=0;na<4;na++){
            sacc[na][0]=__expf(sacc[na][0]-mn0); sacc[na][1]=__expf(sacc[na][1]-mn0);
            sacc[na][2]=__expf(sacc[na][2]-mn1); sacc[na][3]=__expf(sacc[na][3]-mn1);
            ps0+=sacc[na][0]+sacc[na][1]; ps1+=sacc[na][2]+sacc[na][3];
        }
        ps0+=__shfl_xor_sync(0xffffffffu,ps0,1); ps0+=__shfl_xor_sync(0xffffffffu,ps0,2);
        ps1+=__shfl_xor_sync(0xffffffffu,ps1,1); ps1+=__shfl_xor_sync(0xffffffffu,ps1,2);
        s0+=ps0; s1+=ps1;
        #pragma unroll
        for (int na=0;na<8;na++){
            acc_o[na][0]*=r0s; acc_o[na][1]*=r0s; acc_o[na][2]*=r1s; acc_o[na][3]*=r1s;
        }
        // PV: P from registers
        #pragma unroll
        for (int ks=0;ks<2;ks++){
            u32 pa[4], pl2[4];
            pa[0]=split_pair(sacc[2*ks][0],  sacc[2*ks][1],  pl2[0]);
            pa[1]=split_pair(sacc[2*ks][2],  sacc[2*ks][3],  pl2[1]);
            pa[2]=split_pair(sacc[2*ks+1][0],sacc[2*ks+1][1],pl2[2]);
            pa[3]=split_pair(sacc[2*ks+1][2],sacc[2*ks+1][3],pl2[3]);
            u32 bh2[8][2], bl2[8][2];
            #pragma unroll
            for (int pp=0;pp<4;pp++){
                u32 r0,r1,r2,r3;
                ldsm4t(r0,r1,r2,r3, bt_addr<72>(Vh, pp*16, ks*16, lane));
                bh2[2*pp][0]=r0; bh2[2*pp][1]=r1; bh2[2*pp+1][0]=r2; bh2[2*pp+1][1]=r3;
                ldsm4t(r0,r1,r2,r3, bt_addr<72>(Vl, pp*16, ks*16, lane));
                bl2[2*pp][0]=r0; bl2[2*pp][1]=r1; bl2[2*pp+1][0]=r2; bl2[2*pp+1][1]=r3;
            }
            #pragma unroll
            for (int na=0;na<8;na++){
                mmabf(acc_o[na], pa[0],pa[1],pa[2],pa[3], bh2[na][0],bh2[na][1]);
                mmabf(acc_o[na], pa[0],pa[1],pa[2],pa[3], bl2[na][0],bl2[na][1]);
                mmabf(acc_o[na], pl2[0],pl2[1],pl2[2],pl2[3], bh2[na][0],bh2[na][1]);
            }
        }
    }
    // epilogue
    float i0=1.f/s0, i1=1.f/s1;
    #pragma unroll
    for (int na=0;na<8;na++){
        int col=na*8+2*gq;
        size_t o0=(size_t)(b*CTX+rg0)*DIMS + h*HD + col;
        size_t o1=(size_t)(b*CTX+rg0+8)*DIMS + h*HD + col;
        u32 lo,hi;
        hi=split_pair(acc_o[na][0]*i0, acc_o[na][1]*i0, lo);
        *(u32*)(avh_g+o0)=hi; *(u32*)(avl_g+o0)=lo;
        hi=split_pair(acc_o[na][2]*i1, acc_o[na][3]*i1, lo);
        *(u32*)(avh_g+o1)=hi; *(u32*)(avl_g+o1)=lo;
    }
}

// ============================================================
extern "C" void kernel_launch(void* const* d_in, const int* in_sizes, int n_in,
                              void* d_out, int out_size)
{
    const float* x    = (const float*)d_in[0];
    const float* Wq   = (const float*)d_in[1];
    const float* bq   = (const float*)d_in[2];
    const float* Wk   = (const float*)d_in[3];
    const float* Wv   = (const float*)d_in[4];
    const float* bv   = (const float*)d_in[5];
    const float* Wout = (const float*)d_in[6];
    const float* bout = (const float*)d_in[7];
    const float* factor = (const float*)d_in[8];

    u16 *xh,*xl,*wqh,*wql,*wkh,*wkl,*wvh,*wvl,*woh,*wol,*wth,*wtl,*w2h,*w2l;
    u16 *qh,*ql,*kh,*kl,*vh,*vl,*avh,*avl;
    float *b2,*kc0,*qkfb;
    cudaGetSymbolAddress((void**)&xh,  g_xh);  cudaGetSymbolAddress((void**)&xl,  g_xl);
    cudaGetSymbolAddress((void**)&wqh, g_Wqh); cudaGetSymbolAddress((void**)&wql, g_Wql);
    cudaGetSymbolAddress((void**)&wkh, g_Wkh); cudaGetSymbolAddress((void**)&wkl, g_Wkl);
    cudaGetSymbolAddress((void**)&wvh, g_Wvh); cudaGetSymbolAddress((void**)&wvl, g_Wvl);
    cudaGetSymbolAddress((void**)&woh, g_Woh); cudaGetSymbolAddress((void**)&wol, g_Wol);
    cudaGetSymbolAddress((void**)&wth, g_Wth); cudaGetSymbolAddress((void**)&wtl, g_Wtl);
    cudaGetSymbolAddress((void**)&w2h, g_W2h); cudaGetSymbolAddress((void**)&w2l, g_W2l);
    cudaGetSymbolAddress((void**)&qh,  g_qh);  cudaGetSymbolAddress((void**)&ql,  g_ql);
    cudaGetSymbolAddress((void**)&kh,  g_kh);  cudaGetSymbolAddress((void**)&kl,  g_kl);
    cudaGetSymbolAddress((void**)&vh,  g_vh);  cudaGetSymbolAddress((void**)&vl,  g_vl);
    cudaGetSymbolAddress((void**)&avh, g_avh); cudaGetSymbolAddress((void**)&avl, g_avl);
    cudaGetSymbolAddress((void**)&b2,  g_b2);
    cudaGetSymbolAddress((void**)&kc0, g_kc0);
    cudaGetSymbolAddress((void**)&qkfb, g_qk_fallback);

    float* out = (float*)d_out;
    float* qkdst = ((size_t)out_size >= (size_t)OUT_ELEMS + QK_ELEMS)
                 ? (out + OUT_ELEMS) : qkfb;

    const int GSM = 98304;
    cudaFuncSetAttribute(gemm_qkv,       cudaFuncAttributeMaxDynamicSharedMemorySize, GSM);
    cudaFuncSetAttribute(gemm_one<false>,cudaFuncAttributeMaxDynamicSharedMemorySize, GSM);
    cudaFuncSetAttribute(gemm_one<true>, cudaFuncAttributeMaxDynamicSharedMemorySize, GSM);
    cudaFuncSetAttribute(attn_fused,     cudaFuncAttributeMaxDynamicSharedMemorySize, ATT_SMEM);

    // converts
    conv_split<<<2048,256>>>(x, xh, xl, MROWS*DIMS);
    WPack wp;
    wp.s[0]=Wq;  wp.h[0]=wqh; wp.l[0]=wql;
    wp.s[1]=Wk;  wp.h[1]=wkh; wp.l[1]=wkl;
    wp.s[2]=Wv;  wp.h[2]=wvh; wp.l[2]=wvl;
    wp.s[3]=Wout;wp.h[3]=woh; wp.l[3]=wol;
    conv_w4<<<dim3(512,4),256>>>(wp);
    conv_split_t<<<dim3(32,32),256>>>(Wout, wth, wtl);
    bias2_k<<<128,256>>>(Wout, bout, b2);

    // W2 = Wout @ Wout
    gemm_one<false><<<dim3(8,8), 256, GSM>>>(woh, wol, wth, wtl, nullptr, w2h, w2l, nullptr);

    // fused QKV projections
    gemm_qkv<<<dim3(8,32,3), 256, GSM>>>(xh,xl, wqh,wql,wkh,wkl,wvh,wvl,
                                         bq,bv, qh,ql,kh,kl,vh,vl, kc0);

    // fused attention (spills qk)
    attn_fused<<<dim3(16,32), 256, ATT_SMEM>>>(qh,ql,kh,kl,vh,vl, kc0, factor, qkdst, avh, avl);

    // out = wv @ W2^T + b2
    gemm_one<true><<<dim3(8,32), 256, GSM>>>(avh, avl, w2h, w2l, b2, nullptr, nullptr, out);
}

// round 17
// speedup vs baseline: 1.0603x; 1.0427x over previous
#include <cuda_runtime.h>
#include <cuda_bf16.h>
#include <math.h>
#include <stdint.h>

#define DIMS 1024
#define HEAD 16
#define HD   64
#define CTX  2048
#define BATCH 2
#define MROWS (BATCH*CTX)
#define OUT_ELEMS (MROWS*DIMS)
#define QK_ELEMS  ((size_t)BATCH*HEAD*CTX*CTX)

typedef unsigned short u16;
typedef unsigned int   u32;

// ---- scratch ----
__device__ u16 g_xh [MROWS*DIMS], g_xl [MROWS*DIMS];
__device__ u16 g_Wqh[DIMS*DIMS],  g_Wql[DIMS*DIMS];
__device__ u16 g_Wkh[DIMS*DIMS],  g_Wkl[DIMS*DIMS];
__device__ u16 g_Wvh[DIMS*DIMS],  g_Wvl[DIMS*DIMS];
__device__ u16 g_Woh[DIMS*DIMS],  g_Wol[DIMS*DIMS];
__device__ u16 g_Wth[DIMS*DIMS],  g_Wtl[DIMS*DIMS];
__device__ u16 g_W2h[DIMS*DIMS],  g_W2l[DIMS*DIMS];
__device__ float g_b2[DIMS];
__device__ u16 g_qh [MROWS*DIMS], g_ql [MROWS*DIMS];
__device__ u16 g_kh [MROWS*DIMS], g_kl [MROWS*DIMS];
__device__ u16 g_vh [MROWS*DIMS], g_vl [MROWS*DIMS];
__device__ u16 g_avh[MROWS*DIMS], g_avl[MROWS*DIMS];
__device__ float g_kc0[HEAD*MROWS];
__device__ float g_qk_fallback[QK_ELEMS];

// ---- helpers ----
__device__ __forceinline__ u32 smaddr(const void* p){ return (u32)__cvta_generic_to_shared(p); }
__device__ __forceinline__ void ldsm4(u32&r0,u32&r1,u32&r2,u32&r3,u32 a){
    asm volatile("ldmatrix.sync.aligned.m8n8.x4.shared.b16 {%0,%1,%2,%3},[%4];"
        :"=r"(r0),"=r"(r1),"=r"(r2),"=r"(r3):"r"(a));
}
__device__ __forceinline__ void ldsm4t(u32&r0,u32&r1,u32&r2,u32&r3,u32 a){
    asm volatile("ldmatrix.sync.aligned.m8n8.x4.trans.shared.b16 {%0,%1,%2,%3},[%4];"
        :"=r"(r0),"=r"(r1),"=r"(r2),"=r"(r3):"r"(a));
}
__device__ __forceinline__ void mmabf(float c[4],
    u32 a0,u32 a1,u32 a2,u32 a3,u32 b0,u32 b1){
    asm volatile("mma.sync.aligned.m16n8k16.row.col.f32.bf16.bf16.f32 "
        "{%0,%1,%2,%3},{%4,%5,%6,%7},{%8,%9},{%0,%1,%2,%3};"
        :"+f"(c[0]),"+f"(c[1]),"+f"(c[2]),"+f"(c[3])
        :"r"(a0),"r"(a1),"r"(a2),"r"(a3),"r"(b0),"r"(b1));
}
__device__ __forceinline__ u32 packbf(float x, float y){
    __nv_bfloat162 t = __floats2bfloat162_rn(x,y);
    return *reinterpret_cast<u32*>(&t);
}
__device__ __forceinline__ u32 split_pair(float v0, float v1, u32& lo){
    __nv_bfloat16 h0=__float2bfloat16(v0), h1=__float2bfloat16(v1);
    float l0 = v0-__bfloat162float(h0), l1 = v1-__bfloat162float(h1);
    lo = packbf(l0,l1);
    __nv_bfloat162 hh; hh.x=h0; hh.y=h1;
    return *reinterpret_cast<u32*>(&hh);
}
__device__ __forceinline__ void cpa16(u32 dst, const void* src){
    asm volatile("cp.async.cg.shared.global [%0],[%1],16;"::"r"(dst),"l"(src));
}
#define CPA_COMMIT() asm volatile("cp.async.commit_group;"::)
#define CPA_WAIT0()  asm volatile("cp.async.wait_group 0;"::)
#define CPA_WAIT1()  asm volatile("cp.async.wait_group 1;"::)

template<int S>
__device__ __forceinline__ u32 a_addr(u32 base, int r0, int k0, int lane){
    int r = r0 + (lane&7) + ((lane>>3)&1)*8;
    int k = k0 + ((lane>>4)&1)*8;
    return base + (u32)(r*S + k)*2;
}
template<int S>
__device__ __forceinline__ u32 b_addr(u32 base, int n0, int k0, int lane){
    int n = n0 + (lane&7) + ((lane>>4)&1)*8;
    int k = k0 + ((lane>>3)&1)*8;
    return base + (u32)(n*S + k)*2;
}
template<int S>
__device__ __forceinline__ u32 bt_addr(u32 base, int n0, int k0, int lane){
    int k = k0 + (lane&7) + ((lane>>3)&1)*8;
    int n = n0 + ((lane>>4)&1)*8;
    return base + (u32)(k*S + n)*2;
}
__device__ __forceinline__ u32 a_sw(u32 base, int r0, int k0, int lane){
    int r = r0 + (lane&7) + ((lane>>3)&1)*8;
    int c = (k0>>3) + ((lane>>4)&1);
    int ph = c ^ ((r>>1)&3);
    return base + (u32)(r*32 + ph*8)*2;
}
__device__ __forceinline__ u32 b_sw(u32 base, int n0, int k0, int lane){
    int n = n0 + (lane&7) + ((lane>>4)&1)*8;
    int c = (k0>>3) + ((lane>>3)&1);
    int ph = c ^ ((n>>1)&3);
    return base + (u32)(n*32 + ph*8)*2;
}

// ============================================================
// converts
// ============================================================
__global__ void __launch_bounds__(256) conv_split(
    const float* __restrict__ s, u16* __restrict__ h, u16* __restrict__ l, int n)
{
    int i = (blockIdx.x*256 + threadIdx.x)*8;
    if (i >= n) return;
    float4 x0 = *(const float4*)(s+i), x1 = *(const float4*)(s+i+4);
    float xs[8] = {x0.x,x0.y,x0.z,x0.w,x1.x,x1.y,x1.z,x1.w};
    u32 H[4], L[4];
    #pragma unroll
    for (int j=0;j<4;j++) H[j] = split_pair(xs[2*j], xs[2*j+1], L[j]);
    *(uint4*)(h+i) = make_uint4(H[0],H[1],H[2],H[3]);
    *(uint4*)(l+i) = make_uint4(L[0],L[1],L[2],L[3]);
}

struct WPack { const float* s[4]; u16* h[4]; u16* l[4]; };
__global__ void __launch_bounds__(256) conv_w4(WPack p)
{
    int w = blockIdx.y;
    const float* s = p.s[w];
    u16 *h = p.h[w], *l = p.l[w];
    int i = (blockIdx.x*256 + threadIdx.x)*8;
    float4 x0 = *(const float4*)(s+i), x1 = *(const float4*)(s+i+4);
    float xs[8] = {x0.x,x0.y,x0.z,x0.w,x1.x,x1.y,x1.z,x1.w};
    u32 H[4], L[4];
    #pragma unroll
    for (int j=0;j<4;j++) H[j] = split_pair(xs[2*j], xs[2*j+1], L[j]);
    *(uint4*)(h+i) = make_uint4(H[0],H[1],H[2],H[3]);
    *(uint4*)(l+i) = make_uint4(L[0],L[1],L[2],L[3]);
}

__global__ void __launch_bounds__(256) conv_split_t(
    const float* __restrict__ s, u16* __restrict__ h, u16* __restrict__ l)
{
    __shared__ float tile[32][33];
    int bx = blockIdx.x*32, by = blockIdx.y*32;
    int tx = threadIdx.x&31, ty = threadIdx.x>>5;
    for (int i = ty; i < 32; i += 8)
        tile[i][tx] = s[(size_t)(by+i)*DIMS + bx+tx];
    __syncthreads();
    for (int i = ty; i < 32; i += 8) {
        float v = tile[tx][i];
        __nv_bfloat16 hb = __float2bfloat16(v);
        h[(size_t)(bx+i)*DIMS + by+tx] = *(u16*)&hb;
        float lv = v - __bfloat162float(hb);
        __nv_bfloat16 lb = __float2bfloat16(lv);
        l[(size_t)(bx+i)*DIMS + by+tx] = *(u16*)&lb;
    }
}

__global__ void __launch_bounds__(256) bias2_k(
    const float* __restrict__ W, const float* __restrict__ b, float* __restrict__ out)
{
    int n = blockIdx.x*8 + (threadIdx.x>>5);
    int lane = threadIdx.x & 31;
    float s = 0.f;
    for (int k = lane; k < 1024; k += 32) s += b[k] * W[(size_t)n*1024 + k];
    #pragma unroll
    for (int o = 16; o; o >>= 1) s += __shfl_xor_sync(0xffffffffu, s, o);
    if (lane == 0) out[n] = s + b[n];
}

// ============================================================
// bf16x3 GEMM body
// ============================================================
template<bool F32OUT>
__device__ __forceinline__ void gemm_body(
    const u16* __restrict__ Agh, const u16* __restrict__ Agl,
    const u16* __restrict__ Bgh, const u16* __restrict__ Bgl,
    const float* __restrict__ bias,
    u16* __restrict__ Ch, u16* __restrict__ Cl,
    float* __restrict__ Cf, float* __restrict__ kc0,
    int row0, int col0, u16* smp)
{
    int t=threadIdx.x, warp=t>>5, lane=t&31;
    int wm=(warp>>2)*64, wn=(warp&3)*32;
    int gr=lane>>2, gq=lane&3;
    float acc[4][4][4]={};

    int lrow=t>>1, kc2=(t&1)*2;
    const u16* Ash = Agh + (size_t)(row0+lrow)*DIMS + kc2*8;
    const u16* Asl = Agl + (size_t)(row0+lrow)*DIMS + kc2*8;
    const u16* Bsh = Bgh + (size_t)(col0+lrow)*DIMS + kc2*8;
    const u16* Bsl = Bgl + (size_t)(col0+lrow)*DIMS + kc2*8;
    u32 base = smaddr(smp);
    int sw = (lrow>>1)&3;
    u32 d0 = base + (u32)(lrow*32 + (kc2^sw)*8)*2;
    u32 d1 = base + (u32)(lrow*32 + ((kc2+1)^sw)*8)*2;

    auto issue=[&](int it, int st){
        u32 o = (u32)st*32768;
        cpa16(d0+o,        Ash+it*32);  cpa16(d1+o,        Ash+it*32+8);
        cpa16(d0+o+8192,   Asl+it*32);  cpa16(d1+o+8192,   Asl+it*32+8);
        cpa16(d0+o+16384,  Bsh+it*32);  cpa16(d1+o+16384,  Bsh+it*32+8);
        cpa16(d0+o+24576,  Bsl+it*32);  cpa16(d1+o+24576,  Bsl+it*32+8);
        CPA_COMMIT();
    };
    issue(0,0); issue(1,1);

    for (int it=0; it<32; it++){
        int st = it - (it/3)*3;
        CPA_WAIT1();
        __syncthreads();
        if (it+2<32) issue(it+2, (it+2)-((it+2)/3)*3);
        u32 Ah = base + (u32)st*32768;
        u32 Al = Ah+8192, Bh = Ah+16384, Bl = Ah+24576;
        #pragma unroll
        for (int ksi=0;ksi<2;ksi++){
            int kk=ksi*16;
            u32 ah[4][4], al[4][4], bh2[4][2], bl2[4][2];
            #pragma unroll
            for (int m2=0;m2<4;m2++){
                ldsm4(ah[m2][0],ah[m2][1],ah[m2][2],ah[m2][3], a_sw(Ah, wm+m2*16, kk, lane));
                ldsm4(al[m2][0],al[m2][1],al[m2][2],al[m2][3], a_sw(Al, wm+m2*16, kk, lane));
            }
            #pragma unroll
            for (int pp=0;pp<2;pp++){
                u32 r0,r1,r2,r3;
                ldsm4(r0,r1,r2,r3, b_sw(Bh, wn+pp*16, kk, lane));
                bh2[2*pp][0]=r0; bh2[2*pp][1]=r1; bh2[2*pp+1][0]=r2; bh2[2*pp+1][1]=r3;
                ldsm4(r0,r1,r2,r3, b_sw(Bl, wn+pp*16, kk, lane));
                bl2[2*pp][0]=r0; bl2[2*pp][1]=r1; bl2[2*pp+1][0]=r2; bl2[2*pp+1][1]=r3;
            }
            #pragma unroll
            for (int m2=0;m2<4;m2++)
                #pragma unroll
                for (int na=0;na<4;na++){
                    mmabf(acc[m2][na], ah[m2][0],ah[m2][1],ah[m2][2],ah[m2][3], bh2[na][0],bh2[na][1]);
                    mmabf(acc[m2][na], ah[m2][0],ah[m2][1],ah[m2][2],ah[m2][3], bl2[na][0],bl2[na][1]);
                    mmabf(acc[m2][na], al[m2][0],al[m2][1],al[m2][2],al[m2][3], bh2[na][0],bh2[na][1]);
                }
        }
    }
    #pragma unroll
    for (int m2=0;m2<4;m2++)
        #pragma unroll
        for (int na=0;na<4;na++){
            int r  = row0+wm+m2*16+gr;
            int cn = col0+wn+na*8+2*gq;
            float b0v = bias? bias[cn]:0.f, b1v = bias? bias[cn+1]:0.f;
            float v0=acc[m2][na][0]+b0v, v1=acc[m2][na][1]+b1v;
            float v2=acc[m2][na][2]+b0v, v3=acc[m2][na][3]+b1v;
            if (F32OUT){
                *(float2*)(Cf+(size_t)r*DIMS+cn)     = make_float2(v0,v1);
                *(float2*)(Cf+(size_t)(r+8)*DIMS+cn) = make_float2(v2,v3);
            } else {
                u32 lo,hi;
                hi=split_pair(v0,v1,lo);
                *(u32*)(Ch+(size_t)r*DIMS+cn)=hi;  *(u32*)(Cl+(size_t)r*DIMS+cn)=lo;
                hi=split_pair(v2,v3,lo);
                *(u32*)(Ch+(size_t)(r+8)*DIMS+cn)=hi; *(u32*)(Cl+(size_t)(r+8)*DIMS+cn)=lo;
                if (kc0 && gq==0 && (((wn+na*8)&63)==0)){
                    int hh = cn>>6;
                    kc0[hh*MROWS + r]   = v0;
                    kc0[hh*MROWS + r+8] = v2;
                }
            }
        }
}

template<bool F32OUT>
__global__ void __launch_bounds__(256,2) gemm_one(
    const u16* Agh, const u16* Agl, const u16* Bgh, const u16* Bgl,
    const float* bias, u16* Ch, u16* Cl, float* Cf)
{
    extern __shared__ u16 smp[];
    gemm_body<F32OUT>(Agh,Agl,Bgh,Bgl,bias,Ch,Cl,Cf,nullptr,
                      blockIdx.y*128, blockIdx.x*128, smp);
}

__global__ void __launch_bounds__(256,2) gemm_qkv(
    const u16* xh, const u16* xl,
    const u16* wqh, const u16* wql, const u16* wkh, const u16* wkl,
    const u16* wvh, const u16* wvl,
    const float* bq, const float* bv,
    u16* qh, u16* ql, u16* kh, u16* kl, u16* vh, u16* vl, float* kc0)
{
    extern __shared__ u16 smp[];
    int z = blockIdx.z;
    const u16* Bh = (z==0)? wqh : (z==1)? wkh : wvh;
    const u16* Bl = (z==0)? wql : (z==1)? wkl : wvl;
    const float* bias = (z==0)? bq : (z==1)? nullptr : bv;
    u16* Ch = (z==0)? qh : (z==1)? kh : vh;
    u16* Cl = (z==0)? ql : (z==1)? kl : vl;
    float* kc = (z==1)? kc0 : nullptr;
    gemm_body<false>(xh,xl,Bh,Bl,bias,Ch,Cl,nullptr,kc,
                     blockIdx.y*128, blockIdx.x*128, smp);
}

// ============================================================
// Fused attention v3: NO-MAX softmax (logits bounded, exp safe in fp32).
// 128 q-rows/CTA, 8 warps x 16 rows, 32-key chunks, ring-3 cp.async,
// P in registers, per-thread partial row sums reduced once in epilogue.
// smem: Qh 0, Ql 9216, KV 18432 (+9216/buf x3), gz @46080. 92544 B.
// ============================================================
#define ATT_SMEM 92544

__global__ void __launch_bounds__(256,2) attn_fused(
    const u16* __restrict__ qh_g, const u16* __restrict__ ql_g,
    const u16* __restrict__ kh_g, const u16* __restrict__ kl_g,
    const u16* __restrict__ vh_g, const u16* __restrict__ vl_g,
    const float* __restrict__ kc0, const float* __restrict__ factor,
    float* __restrict__ qk, u16* __restrict__ avh_g, u16* __restrict__ avl_g)
{
    extern __shared__ u16 sma[];
    u16 *Qh_p = sma, *Ql_p = sma+9216, *KV_p = sma+18432;
    float* gzb = (float*)(sma + 46080);

    int t=threadIdx.x, warp=t>>5, lane=t&31;
    int qb=blockIdx.x, bh=blockIdx.y, b=bh>>4, h=bh&15;
    int row0=qb*128, wm=warp*16;
    int gr=lane>>2, gq=lane&3;

    float zfac; { float f=*factor; zfac=fminf(fmaxf(log1pf(expf(f)),0.f),0.001f); }

    // stage Q (grouped with KV chunk 0)
    {
        int row=t>>1, half=(t&1)*32;
        const u16* sh = qh_g + (size_t)(b*CTX+row0+row)*DIMS + h*HD + half;
        const u16* sl = ql_g + (size_t)(b*CTX+row0+row)*DIMS + h*HD + half;
        u32 dh = smaddr(Qh_p) + (u32)(row*72+half)*2;
        u32 dl = smaddr(Ql_p) + (u32)(row*72+half)*2;
        #pragma unroll
        for (int c=0;c<32;c+=8){ cpa16(dh+c*2, sh+c); cpa16(dl+c*2, sl+c); }
    }
    int krow=t>>3, kseg=(t&7)*8;
    const float* kc0p = kc0 + h*MROWS + b*CTX;
    auto issue_kv=[&](int it, int buf){
        size_t g = (size_t)(b*CTX + it*32 + krow)*DIMS + h*HD + kseg;
        u32 d = smaddr(KV_p) + (u32)buf*18432 + (u32)(krow*72+kseg)*2;
        cpa16(d,        kh_g+g);
        cpa16(d+4608,   kl_g+g);
        cpa16(d+9216,   vh_g+g);
        cpa16(d+13824,  vl_g+g);
        if (t<8) cpa16(smaddr(gzb) + (u32)buf*128 + t*16, kc0p + it*32 + t*4);
        CPA_COMMIT();
    };
    issue_kv(0,0);
    issue_kv(1,1);

    float s0=0.f, s1=0.f;           // per-thread partial row sums (no max needed)
    float acc_o[8][4]={};
    u32 qfh[4][4], qfl[4][4];
    float* Lb = qk + (size_t)bh*CTX*CTX;
    int rg0 = row0+wm+gr;

    for (int it=0; it<64; it++){
        int buf = it - (it/3)*3;
        u32 Kh = smaddr(KV_p) + (u32)buf*18432;
        u32 Kl = Kh+4608, Vh = Kh+9216, Vl = Kh+13824;
        CPA_WAIT1();
        __syncthreads();
        if (it==0){
            #pragma unroll
            for (int ks=0;ks<4;ks++){
                ldsm4(qfh[ks][0],qfh[ks][1],qfh[ks][2],qfh[ks][3], a_addr<72>(smaddr(Qh_p), wm, ks*16, lane));
                ldsm4(qfl[ks][0],qfl[ks][1],qfl[ks][2],qfl[ks][3], a_addr<72>(smaddr(Ql_p), wm, ks*16, lane));
            }
        }
        if (it+2<64){ int nb=(it+2)-((it+2)/3)*3; issue_kv(it+2, nb); }

        // S = Q @ K^T  (16 rows x 32 keys per warp)
        float sacc[4][4]={};
        #pragma unroll
        for (int ks=0;ks<4;ks++){
            u32 bh2[4][2], bl2[4][2];
            #pragma unroll
            for (int pp=0;pp<2;pp++){
                u32 r0,r1,r2,r3;
                ldsm4(r0,r1,r2,r3, b_addr<72>(Kh, pp*16, ks*16, lane));
                bh2[2*pp][0]=r0; bh2[2*pp][1]=r1; bh2[2*pp+1][0]=r2; bh2[2*pp+1][1]=r3;
                ldsm4(r0,r1,r2,r3, b_addr<72>(Kl, pp*16, ks*16, lane));
                bl2[2*pp][0]=r0; bl2[2*pp][1]=r1; bl2[2*pp+1][0]=r2; bl2[2*pp+1][1]=r3;
            }
            #pragma unroll
            for (int na=0;na<4;na++){
                mmabf(sacc[na], qfh[ks][0],qfh[ks][1],qfh[ks][2],qfh[ks][3], bh2[na][0],bh2[na][1]);
                mmabf(sacc[na], qfh[ks][0],qfh[ks][1],qfh[ks][2],qfh[ks][3], bl2[na][0],bl2[na][1]);
                mmabf(sacc[na], qfl[ks][0],qfl[ks][1],qfl[ks][2],qfl[ks][3], bh2[na][0],bh2[na][1]);
            }
        }
        // gate + scale + spill qk + exp (no max: logits bounded, fp32-safe)
        const float* gz = gzb + buf*32;
        int kb = it*32;
        #pragma unroll
        for (int na=0;na<4;na++){
            int col=na*8+2*gq;
            float2 gv = *(const float2*)(gz + col);
            float z0 = ((gv.x==0.f)? zfac:1.f)*0.125f;
            float z1 = ((gv.y==0.f)? zfac:1.f)*0.125f;
            sacc[na][0]*=z0; sacc[na][1]*=z1; sacc[na][2]*=z0; sacc[na][3]*=z1;
            *(float2*)(Lb+(size_t)rg0*CTX+kb+col)     = make_float2(sacc[na][0],sacc[na][1]);
            *(float2*)(Lb+(size_t)(rg0+8)*CTX+kb+col) = make_float2(sacc[na][2],sacc[na][3]);
            sacc[na][0]=__expf(sacc[na][0]); sacc[na][1]=__expf(sacc[na][1]);
            sacc[na][2]=__expf(sacc[na][2]); sacc[na][3]=__expf(sacc[na][3]);
            s0+=sacc[na][0]+sacc[na][1]; s1+=sacc[na][2]+sacc[na][3];
        }
        // PV: P from registers (S C-layout == PV A-layout)
        #pragma unroll
        for (int ks=0;ks<2;ks++){
            u32 pa[4], pl2[4];
            pa[0]=split_pair(sacc[2*ks][0],  sacc[2*ks][1],  pl2[0]);
            pa[1]=split_pair(sacc[2*ks][2],  sacc[2*ks][3],  pl2[1]);
            pa[2]=split_pair(sacc[2*ks+1][0],sacc[2*ks+1][1],pl2[2]);
            pa[3]=split_pair(sacc[2*ks+1][2],sacc[2*ks+1][3],pl2[3]);
            u32 bh2[8][2], bl2[8][2];
            #pragma unroll
            for (int pp=0;pp<4;pp++){
                u32 r0,r1,r2,r3;
                ldsm4t(r0,r1,r2,r3, bt_addr<72>(Vh, pp*16, ks*16, lane));
                bh2[2*pp][0]=r0; bh2[2*pp][1]=r1; bh2[2*pp+1][0]=r2; bh2[2*pp+1][1]=r3;
                ldsm4t(r0,r1,r2,r3, bt_addr<72>(Vl, pp*16, ks*16, lane));
                bl2[2*pp][0]=r0; bl2[2*pp][1]=r1; bl2[2*pp+1][0]=r2; bl2[2*pp+1][1]=r3;
            }
            #pragma unroll
            for (int na=0;na<8;na++){
                mmabf(acc_o[na], pa[0],pa[1],pa[2],pa[3], bh2[na][0],bh2[na][1]);
                mmabf(acc_o[na], pa[0],pa[1],pa[2],pa[3], bl2[na][0],bl2[na][1]);
                mmabf(acc_o[na], pl2[0],pl2[1],pl2[2],pl2[3], bh2[na][0],bh2[na][1]);
            }
        }
    }
    // epilogue: reduce row sums across the 4-thread groups once, normalize
    s0 += __shfl_xor_sync(0xffffffffu, s0, 1);
    s0 += __shfl_xor_sync(0xffffffffu, s0, 2);
    s1 += __shfl_xor_sync(0xffffffffu, s1, 1);
    s1 += __shfl_xor_sync(0xffffffffu, s1, 2);
    float i0=1.f/s0, i1=1.f/s1;
    #pragma unroll
    for (int na=0;na<8;na++){
        int col=na*8+2*gq;
        size_t o0=(size_t)(b*CTX+rg0)*DIMS + h*HD + col;
        size_t o1=(size_t)(b*CTX+rg0+8)*DIMS + h*HD + col;
        u32 lo,hi;
        hi=split_pair(acc_o[na][0]*i0, acc_o[na][1]*i0, lo);
        *(u32*)(avh_g+o0)=hi; *(u32*)(avl_g+o0)=lo;
        hi=split_pair(acc_o[na][2]*i1, acc_o[na][3]*i1, lo);
        *(u32*)(avh_g+o1)=hi; *(u32*)(avl_g+o1)=lo;
    }
}

// ============================================================
extern "C" void kernel_launch(void* const* d_in, const int* in_sizes, int n_in,
                              void* d_out, int out_size)
{
    const float* x    = (const float*)d_in[0];
    const float* Wq   = (const float*)d_in[1];
    const float* bq   = (const float*)d_in[2];
    const float* Wk   = (const float*)d_in[3];
    const float* Wv   = (const float*)d_in[4];
    const float* bv   = (const float*)d_in[5];
    const float* Wout = (const float*)d_in[6];
    const float* bout = (const float*)d_in[7];
    const float* factor = (const float*)d_in[8];

    u16 *xh,*xl,*wqh,*wql,*wkh,*wkl,*wvh,*wvl,*woh,*wol,*wth,*wtl,*w2h,*w2l;
    u16 *qh,*ql,*kh,*kl,*vh,*vl,*avh,*avl;
    float *b2,*kc0,*qkfb;
    cudaGetSymbolAddress((void**)&xh,  g_xh);  cudaGetSymbolAddress((void**)&xl,  g_xl);
    cudaGetSymbolAddress((void**)&wqh, g_Wqh); cudaGetSymbolAddress((void**)&wql, g_Wql);
    cudaGetSymbolAddress((void**)&wkh, g_Wkh); cudaGetSymbolAddress((void**)&wkl, g_Wkl);
    cudaGetSymbolAddress((void**)&wvh, g_Wvh); cudaGetSymbolAddress((void**)&wvl, g_Wvl);
    cudaGetSymbolAddress((void**)&woh, g_Woh); cudaGetSymbolAddress((void**)&wol, g_Wol);
    cudaGetSymbolAddress((void**)&wth, g_Wth); cudaGetSymbolAddress((void**)&wtl, g_Wtl);
    cudaGetSymbolAddress((void**)&w2h, g_W2h); cudaGetSymbolAddress((void**)&w2l, g_W2l);
    cudaGetSymbolAddress((void**)&qh,  g_qh);  cudaGetSymbolAddress((void**)&ql,  g_ql);
    cudaGetSymbolAddress((void**)&kh,  g_kh);  cudaGetSymbolAddress((void**)&kl,  g_kl);
    cudaGetSymbolAddress((void**)&vh,  g_vh);  cudaGetSymbolAddress((void**)&vl,  g_vl);
    cudaGetSymbolAddress((void**)&avh, g_avh); cudaGetSymbolAddress((void**)&avl, g_avl);
    cudaGetSymbolAddress((void**)&b2,  g_b2);
    cudaGetSymbolAddress((void**)&kc0, g_kc0);
    cudaGetSymbolAddress((void**)&qkfb, g_qk_fallback);

    float* out = (float*)d_out;
    float* qkdst = ((size_t)out_size >= (size_t)OUT_ELEMS + QK_ELEMS)
                 ? (out + OUT_ELEMS) : qkfb;

    const int GSM = 98304;
    cudaFuncSetAttribute(gemm_qkv,       cudaFuncAttributeMaxDynamicSharedMemorySize, GSM);
    cudaFuncSetAttribute(gemm_one<false>,cudaFuncAttributeMaxDynamicSharedMemorySize, GSM);
    cudaFuncSetAttribute(gemm_one<true>, cudaFuncAttributeMaxDynamicSharedMemorySize, GSM);
    cudaFuncSetAttribute(attn_fused,     cudaFuncAttributeMaxDynamicSharedMemorySize, ATT_SMEM);

    // converts
    conv_split<<<2048,256>>>(x, xh, xl, MROWS*DIMS);
    WPack wp;
    wp.s[0]=Wq;  wp.h[0]=wqh; wp.l[0]=wql;
    wp.s[1]=Wk;  wp.h[1]=wkh; wp.l[1]=wkl;
    wp.s[2]=Wv;  wp.h[2]=wvh; wp.l[2]=wvl;
    wp.s[3]=Wout;wp.h[3]=woh; wp.l[3]=wol;
    conv_w4<<<dim3(512,4),256>>>(wp);
    conv_split_t<<<dim3(32,32),256>>>(Wout, wth, wtl);
    bias2_k<<<128,256>>>(Wout, bout, b2);

    // W2 = Wout @ Wout
    gemm_one<false><<<dim3(8,8), 256, GSM>>>(woh, wol, wth, wtl, nullptr, w2h, w2l, nullptr);

    // fused QKV projections
    gemm_qkv<<<dim3(8,32,3), 256, GSM>>>(xh,xl, wqh,wql,wkh,wkl,wvh,wvl,
                                         bq,bv, qh,ql,kh,kl,vh,vl, kc0);

    // fused attention (spills qk)
    attn_fused<<<dim3(16,32), 256, ATT_SMEM>>>(qh,ql,kh,kl,vh,vl, kc0, factor, qkdst, avh, avl);

    // out = wv @ W2^T + b2
    gemm_one<true><<<dim3(8,32), 256, GSM>>>(avh, avl, w2h, w2l, b2, nullptr, nullptr, out);
}